// round 11
// baseline (speedup 1.0000x reference)
#include <cuda_runtime.h>

#define NBATCH 2048
#define NCLS 62
#define THREADS 512
#define TOT4 (62 * 128)       // float4 per batch across all 62 channels
#define INV_LOG_NCLS 0.24233102611194615f   // 1 / ln(62)

// concat channel c (global 0..61) -> output row r (verified)
__constant__ int c_orow[62] = {
    1, 0, 2, 3, 4, 6, 7, 8, 9, 10, 11, 12,
    5, 13, 14, 15, 21, 22, 23, 24, 30, 31, 32, 33, 39, 40, 41, 42, 48, 49,
    16, 17, 18, 19, 20, 25, 26, 27, 28, 29, 34, 35, 36, 37, 38, 43, 44, 45, 46, 47,
    50, 51, 52, 53, 54, 55, 56, 57, 58, 59, 60, 61
};

__global__ __launch_bounds__(THREADS, 2)
void lgl_fused_kernel(
    const float* __restrict__ x1, const float* __restrict__ x2,
    const float* __restrict__ x3, const float* __restrict__ x4,
    const float* __restrict__ g,
    const float* __restrict__ l1, const float* __restrict__ l2,
    const float* __restrict__ l3, const float* __restrict__ l4,
    const float* __restrict__ W1, const float* __restrict__ b1,
    const float* __restrict__ W2, const float* __restrict__ b2,
    const float* __restrict__ W3, const float* __restrict__ b3,
    const float* __restrict__ W4, const float* __restrict__ b4,
    float* __restrict__ out)
{
    __shared__ float red[16][2];
    __shared__ float s_conf[4];
    __shared__ float s_uf[2];

    const int b     = blockIdx.x >> 1;
    const int h     = blockIdx.x & 1;     // 0: G1+G2 (ch 0..29), 1: G3+G4 (ch 30..61)
    const int tid   = threadIdx.x;
    const int lane  = tid & 31;
    const int warp  = tid >> 5;
    const int cbase = h ? 30 : 0;
    const int split = h ? 20 : 12;        // local channel where 2nd group starts
    const int n4    = (h ? 32 : 30) * 128;

    // ---- hoisted scalar loads (latency hides under phase 1) ----
    float la0 = -1e30f, la1 = -1e30f;
    if (warp >= 1 && warp <= 4) {
        const float* lg = (warp == 1 ? l1 : warp == 2 ? l2 : warp == 3 ? l3 : l4)
                          + (size_t)b * NCLS;
        if (lane < NCLS)      la0 = __ldg(lg + lane);
        if (lane + 32 < NCLS) la1 = __ldg(lg + lane + 32);
    }
    float my_bias = 0.f;
    if (warp == 0 && lane < 2) {
        const float* bp = h ? (lane ? b4 : b3) : (lane ? b2 : b1);
        my_bias = __ldg(bp);
    }

    const float4* xav = (const float4*)(h ? x3 : x1);   // first group of this half
    const float4* xbv = (const float4*)(h ? x4 : x2);   // second group
    const float4* wav = (const float4*)(h ? W3 : W1);
    const float4* wbv = (const float4*)(h ? W4 : W2);
    const int cha = h ? 20 : 12;          // channels in first group
    const int chb = h ? 12 : 18;          // channels in second group
    const float4* gvp = (const float4*)g + (size_t)b * TOT4;
    float4* ovp = (float4*)(out + 4 * NBATCH) + (size_t)b * TOT4;

    // ---- Phase 1: stream x-half into REGISTERS + per-group dot (no smem) ----
    float pa = 0.f, pb = 0.f;
    float4 xv[8];
#pragma unroll
    for (int k = 0; k < 8; k++) {
        const int idx = tid + THREADS * k;
        if (idx < n4) {
            const int c = idx >> 7;       // local channel
            const int d = idx & 127;
            const float4* xp;
            const float4* wp;
            if (c < split) { xp = xav + ((size_t)b * cha + c        ) * 128 + d; wp = wav + (c        ) * 128 + d; }
            else           { xp = xbv + ((size_t)b * chb + (c-split)) * 128 + d; wp = wbv + (c - split) * 128 + d; }
            float4 v = __ldcs(xp);
            float4 w = *wp;
            xv[k] = v;
            float dp = v.x * w.x + v.y * w.y + v.z * w.z + v.w * w.w;
            pa += (c < split) ? dp : 0.f;
            pb += (c < split) ? 0.f : dp;
        }
    }

    // ---- confidences (warps 1..4; logits resident; fast-math) ----
    if (warp >= 1 && warp <= 4) {
        const int q = warp - 1;
        float m = fmaxf(la0, la1);
#pragma unroll
        for (int o = 16; o > 0; o >>= 1)
            m = fmaxf(m, __shfl_xor_sync(0xffffffffu, m, o));
        float e0 = (lane < NCLS)      ? __expf(la0 - m) : 0.f;
        float e1 = (lane + 32 < NCLS) ? __expf(la1 - m) : 0.f;
        float s = e0 + e1;
#pragma unroll
        for (int o = 16; o > 0; o >>= 1)
            s += __shfl_xor_sync(0xffffffffu, s, o);
        const float inv = 1.f / s;           // == max_p
        float pp0 = e0 * inv, pp1 = e1 * inv;
        float t = 0.f;
        if (lane < NCLS)      t += pp0 * __logf(pp0 + 1e-8f);
        if (lane + 32 < NCLS) t += pp1 * __logf(pp1 + 1e-8f);
#pragma unroll
        for (int o = 16; o > 0; o >>= 1)
            t += __shfl_xor_sync(0xffffffffu, t, o);
        const float norm_ent = (-t) * INV_LOG_NCLS;
        if (lane == 0) s_conf[q] = inv * (1.f - norm_ent);
    }

    // ---- dot partial reduce (all 16 warps) ----
#pragma unroll
    for (int o = 16; o > 0; o >>= 1) {
        pa += __shfl_xor_sync(0xffffffffu, pa, o);
        pb += __shfl_xor_sync(0xffffffffu, pb, o);
    }
    if (lane == 0) { red[warp][0] = pa; red[warp][1] = pb; }
    __syncthreads();   // covers red[] and s_conf[]

    // ---- finalize: warp 0 ----
    if (warp == 0) {
        const bool ok = lane < 16;
        float va = ok ? red[lane][0] : 0.f;
        float vb = ok ? red[lane][1] : 0.f;
#pragma unroll
        for (int o = 8; o > 0; o >>= 1) {
            va += __shfl_xor_sync(0xffffffffu, va, o);
            vb += __shfl_xor_sync(0xffffffffu, vb, o);
        }
        if (lane < 2) {
            const float c0 = s_conf[0], c1 = s_conf[1], c2 = s_conf[2], c3 = s_conf[3];
            const float cm = fmaxf(fmaxf(c0, c1), fmaxf(c2, c3));
            const float e0 = __expf(c0 - cm), e1 = __expf(c1 - cm),
                        e2 = __expf(c2 - cm), e3 = __expf(c3 - cm);
            const float inv = 1.f / (e0 + e1 + e2 + e3);
            const int gi = 2 * h + lane;                  // global group index
            const float my_e = (gi == 0 ? e0 : gi == 1 ? e1 : gi == 2 ? e2 : e3);
            const float my_v = __shfl_sync(0x3u, lane == 0 ? va : vb, lane);
            const float nc = my_e * inv;
            out[(size_t)gi * NBATCH + b] = nc;            // norm_conf column
            const float u = 1.f / (1.f + __expf(-(my_v + my_bias)));
            s_uf[lane] = u * nc;
        }
    }
    __syncthreads();

    // ---- Phase 4: trans-half = (xv + g) * u_final; g loaded here (MLP=8) ----
    const float ua = s_uf[0], ub = s_uf[1];
#pragma unroll
    for (int k = 0; k < 8; k++) {
        const int idx = tid + THREADS * k;
        if (idx < n4) {
            const int c = idx >> 7;
            const int d = idx & 127;
            const int r = c_orow[cbase + c];
            const float sc = (c < split) ? ua : ub;
            float4 gk = __ldcs(gvp + r * 128 + d);
            float4 v  = xv[k];
            float4 o;
            o.x = (v.x + gk.x) * sc;
            o.y = (v.y + gk.y) * sc;
            o.z = (v.z + gk.z) * sc;
            o.w = (v.w + gk.w) * sc;
            __stcs(ovp + r * 128 + d, o);
        }
    }
}

extern "C" void kernel_launch(void* const* d_in, const int* in_sizes, int n_in,
                              void* d_out, int out_size)
{
    const float* x1 = (const float*)d_in[0];
    const float* x2 = (const float*)d_in[1];
    const float* x3 = (const float*)d_in[2];
    const float* x4 = (const float*)d_in[3];
    const float* g  = (const float*)d_in[4];
    const float* l1 = (const float*)d_in[5];
    const float* l2 = (const float*)d_in[6];
    const float* l3 = (const float*)d_in[7];
    const float* l4 = (const float*)d_in[8];
    const float* W1 = (const float*)d_in[9];
    const float* b1 = (const float*)d_in[10];
    const float* W2 = (const float*)d_in[11];
    const float* b2 = (const float*)d_in[12];
    const float* W3 = (const float*)d_in[13];
    const float* b3 = (const float*)d_in[14];
    const float* W4 = (const float*)d_in[15];
    const float* b4 = (const float*)d_in[16];
    float* out = (float*)d_out;

    lgl_fused_kernel<<<NBATCH * 2, THREADS>>>(
        x1, x2, x3, x4, g, l1, l2, l3, l4,
        W1, b1, W2, b2, W3, b3, W4, b4, out);
}

// round 12
// speedup vs baseline: 1.1543x; 1.1543x over previous
#include <cuda_runtime.h>

#define NBATCH 2048
#define NCLS 62
#define THREADS 512
#define TOT4 (62 * 128)       // float4 per batch across all 62 channels
#define INV_LOG_NCLS 0.24233102611194615f   // 1 / ln(62)

// concat channel c (global 0..61) -> output row r (verified)
__constant__ int c_orow[62] = {
    1, 0, 2, 3, 4, 6, 7, 8, 9, 10, 11, 12,
    5, 13, 14, 15, 21, 22, 23, 24, 30, 31, 32, 33, 39, 40, 41, 42, 48, 49,
    16, 17, 18, 19, 20, 25, 26, 27, 28, 29, 34, 35, 36, 37, 38, 43, 44, 45, 46, 47,
    50, 51, 52, 53, 54, 55, 56, 57, 58, 59, 60, 61
};

template<int H>
__device__ __forceinline__ void lgl_body(
    const float* __restrict__ xa, const float* __restrict__ xb,
    const float* __restrict__ g,
    const float* __restrict__ l1, const float* __restrict__ l2,
    const float* __restrict__ l3, const float* __restrict__ l4,
    const float* __restrict__ Wa, const float* __restrict__ ba,
    const float* __restrict__ Wb, const float* __restrict__ bb,
    float* __restrict__ out, int b, float4* sx,
    float (*red)[2], float* s_conf, float* s_uf)
{
    constexpr int CBASE = H ? 30 : 0;
    constexpr int SPLIT = H ? 20 : 12;    // local channel where 2nd group starts
    constexpr int CHA   = H ? 20 : 12;
    constexpr int CHB   = H ? 12 : 18;
    constexpr int N4    = (CHA + CHB) * 128;   // 4096 (H=1) or 3840 (H=0)

    const int tid  = threadIdx.x;
    const int lane = tid & 31;
    const int warp = tid >> 5;

    // ---- hoisted scalar loads (latency hides under phase 1) ----
    float la0 = -1e30f, la1 = -1e30f;
    if (warp >= 1 && warp <= 4) {
        const float* lg = (warp == 1 ? l1 : warp == 2 ? l2 : warp == 3 ? l3 : l4)
                          + (size_t)b * NCLS;
        if (lane < NCLS)      la0 = __ldg(lg + lane);
        if (lane + 32 < NCLS) la1 = __ldg(lg + lane + 32);
    }
    float my_bias = 0.f;
    if (warp == 0 && lane < 2) my_bias = __ldg(lane ? bb : ba);

    const float4* xav = (const float4*)xa;
    const float4* xbv = (const float4*)xb;
    const float4* wav = (const float4*)Wa;
    const float4* wbv = (const float4*)Wb;
    const float4* gvp = (const float4*)g + (size_t)b * TOT4;
    float4* ovp = (float4*)(out + 4 * NBATCH) + (size_t)b * TOT4;

    // ---- Phase 1: stream x-half -> smem + per-group dot; prefetch g into regs ----
    float pa = 0.f, pb = 0.f;
    float4 gv[8];
#pragma unroll
    for (int k = 0; k < 8; k++) {
        const int idx = tid + THREADS * k;
        const bool act = (N4 == 4096) || (idx < N4);   // compile-time true for H=1, tail-only for H=0
        if (act) {
            const int c = idx >> 7;       // local channel (compile-time strength-reduced)
            const int d = idx & 127;
            const float4* xp;
            const float4* wp;
            if (c < SPLIT) { xp = xav + ((size_t)b * CHA + c        ) * 128 + d; wp = wav + (c        ) * 128 + d; }
            else           { xp = xbv + ((size_t)b * CHB + (c-SPLIT)) * 128 + d; wp = wbv + (c - SPLIT) * 128 + d; }
            float4 v = __ldcs(xp);
            float4 w = *wp;
            sx[idx] = v;
            const int r = c_orow[CBASE + c];
            gv[k] = __ldcs(gvp + r * 128 + d);
            float dp = v.x * w.x + v.y * w.y + v.z * w.z + v.w * w.w;
            pa += (c < SPLIT) ? dp : 0.f;
            pb += (c < SPLIT) ? 0.f : dp;
        }
    }

    // ---- confidences (warps 1..4; logits resident; fast-math) ----
    if (warp >= 1 && warp <= 4) {
        const int q = warp - 1;
        float m = fmaxf(la0, la1);
#pragma unroll
        for (int o = 16; o > 0; o >>= 1)
            m = fmaxf(m, __shfl_xor_sync(0xffffffffu, m, o));
        float e0 = (lane < NCLS)      ? __expf(la0 - m) : 0.f;
        float e1 = (lane + 32 < NCLS) ? __expf(la1 - m) : 0.f;
        float s = e0 + e1;
#pragma unroll
        for (int o = 16; o > 0; o >>= 1)
            s += __shfl_xor_sync(0xffffffffu, s, o);
        const float inv = 1.f / s;           // == max_p
        float pp0 = e0 * inv, pp1 = e1 * inv;
        float t = 0.f;
        if (lane < NCLS)      t += pp0 * __logf(pp0 + 1e-8f);
        if (lane + 32 < NCLS) t += pp1 * __logf(pp1 + 1e-8f);
#pragma unroll
        for (int o = 16; o > 0; o >>= 1)
            t += __shfl_xor_sync(0xffffffffu, t, o);
        const float norm_ent = (-t) * INV_LOG_NCLS;
        if (lane == 0) s_conf[q] = inv * (1.f - norm_ent);
    }

    // ---- dot partial reduce (all 16 warps) ----
#pragma unroll
    for (int o = 16; o > 0; o >>= 1) {
        pa += __shfl_xor_sync(0xffffffffu, pa, o);
        pb += __shfl_xor_sync(0xffffffffu, pb, o);
    }
    if (lane == 0) { red[warp][0] = pa; red[warp][1] = pb; }
    __syncthreads();   // covers red[] and s_conf[]

    // ---- finalize: warp 0 ----
    if (warp == 0) {
        const bool ok = lane < 16;
        float va = ok ? red[lane][0] : 0.f;
        float vb = ok ? red[lane][1] : 0.f;
#pragma unroll
        for (int o = 8; o > 0; o >>= 1) {
            va += __shfl_xor_sync(0xffffffffu, va, o);
            vb += __shfl_xor_sync(0xffffffffu, vb, o);
        }
        if (lane < 2) {
            const float c0 = s_conf[0], c1 = s_conf[1], c2 = s_conf[2], c3 = s_conf[3];
            const float cm = fmaxf(fmaxf(c0, c1), fmaxf(c2, c3));
            const float e0 = __expf(c0 - cm), e1 = __expf(c1 - cm),
                        e2 = __expf(c2 - cm), e3 = __expf(c3 - cm);
            const float inv = 1.f / (e0 + e1 + e2 + e3);
            const int gi = 2 * H + lane;                  // global group index
            const float my_e = (gi == 0 ? e0 : gi == 1 ? e1 : gi == 2 ? e2 : e3);
            const float my_v = __shfl_sync(0x3u, lane == 0 ? va : vb, lane);
            const float nc = my_e * inv;
            out[(size_t)gi * NBATCH + b] = nc;            // norm_conf column
            const float u = 1.f / (1.f + __expf(-(my_v + my_bias)));
            s_uf[lane] = u * nc;
        }
    }
    __syncthreads();

    // ---- Phase 4: trans-half = (x + g) * u_final ----
    const float ua = s_uf[0], ub = s_uf[1];
#pragma unroll
    for (int k = 0; k < 8; k++) {
        const int idx = tid + THREADS * k;
        const bool act = (N4 == 4096) || (idx < N4);
        if (act) {
            const int c = idx >> 7;
            const int d = idx & 127;
            const int r = c_orow[CBASE + c];
            const float sc = (c < SPLIT) ? ua : ub;
            float4 v  = sx[idx];
            float4 gk = gv[k];
            float4 o;
            o.x = (v.x + gk.x) * sc;
            o.y = (v.y + gk.y) * sc;
            o.z = (v.z + gk.z) * sc;
            o.w = (v.w + gk.w) * sc;
            __stcs(ovp + r * 128 + d, o);
        }
    }
}

__global__ __launch_bounds__(THREADS, 2)
void lgl_fused_kernel(
    const float* __restrict__ x1, const float* __restrict__ x2,
    const float* __restrict__ x3, const float* __restrict__ x4,
    const float* __restrict__ g,
    const float* __restrict__ l1, const float* __restrict__ l2,
    const float* __restrict__ l3, const float* __restrict__ l4,
    const float* __restrict__ W1, const float* __restrict__ b1,
    const float* __restrict__ W2, const float* __restrict__ b2,
    const float* __restrict__ W3, const float* __restrict__ b3,
    const float* __restrict__ W4, const float* __restrict__ b4,
    float* __restrict__ out)
{
    extern __shared__ float4 sx[];        // up to 4096 float4 = 65536 B (half tile)
    __shared__ float red[16][2];
    __shared__ float s_conf[4];
    __shared__ float s_uf[2];

    const int b = blockIdx.x >> 1;
    if (blockIdx.x & 1)
        lgl_body<1>(x3, x4, g, l1, l2, l3, l4, W3, b3, W4, b4, out, b, sx, red, s_conf, s_uf);
    else
        lgl_body<0>(x1, x2, g, l1, l2, l3, l4, W1, b1, W2, b2, out, b, sx, red, s_conf, s_uf);
}

extern "C" void kernel_launch(void* const* d_in, const int* in_sizes, int n_in,
                              void* d_out, int out_size)
{
    const float* x1 = (const float*)d_in[0];
    const float* x2 = (const float*)d_in[1];
    const float* x3 = (const float*)d_in[2];
    const float* x4 = (const float*)d_in[3];
    const float* g  = (const float*)d_in[4];
    const float* l1 = (const float*)d_in[5];
    const float* l2 = (const float*)d_in[6];
    const float* l3 = (const float*)d_in[7];
    const float* l4 = (const float*)d_in[8];
    const float* W1 = (const float*)d_in[9];
    const float* b1 = (const float*)d_in[10];
    const float* W2 = (const float*)d_in[11];
    const float* b2 = (const float*)d_in[12];
    const float* W3 = (const float*)d_in[13];
    const float* b3 = (const float*)d_in[14];
    const float* W4 = (const float*)d_in[15];
    const float* b4 = (const float*)d_in[16];
    float* out = (float*)d_out;

    const int smem = 32 * 512 * (int)sizeof(float);   // 65536 B (worst half)
    cudaFuncSetAttribute(lgl_fused_kernel,
                         cudaFuncAttributeMaxDynamicSharedMemorySize, smem);

    lgl_fused_kernel<<<NBATCH * 2, THREADS, smem>>>(
        x1, x2, x3, x4, g, l1, l2, l3, l4,
        W1, b1, W2, b2, W3, b3, W4, b4, out);
}

// round 13
// speedup vs baseline: 1.2423x; 1.0762x over previous
#include <cuda_runtime.h>
#include <cstdint>

#define NBATCH 2048
#define NCLS 62
#define THREADS 512
#define TOT4 (62 * 128)       // float4 per batch across all 62 channels
#define INV_LOG_NCLS 0.24233102611194615f   // 1 / ln(62)

// concat channel c (global 0..61) -> output row r (verified)
__constant__ int c_orow[62] = {
    1, 0, 2, 3, 4, 6, 7, 8, 9, 10, 11, 12,
    5, 13, 14, 15, 21, 22, 23, 24, 30, 31, 32, 33, 39, 40, 41, 42, 48, 49,
    16, 17, 18, 19, 20, 25, 26, 27, 28, 29, 34, 35, 36, 37, 38, 43, 44, 45, 46, 47,
    50, 51, 52, 53, 54, 55, 56, 57, 58, 59, 60, 61
};

__device__ __forceinline__ void cp_async16(uint32_t dst_smem, const void* src) {
    asm volatile("cp.async.cg.shared.global [%0], [%1], 16;"
                 :: "r"(dst_smem), "l"(src) : "memory");
}

__global__ __launch_bounds__(THREADS, 2)
void lgl_fused_kernel(
    const float* __restrict__ x1, const float* __restrict__ x2,
    const float* __restrict__ x3, const float* __restrict__ x4,
    const float* __restrict__ g,
    const float* __restrict__ l1, const float* __restrict__ l2,
    const float* __restrict__ l3, const float* __restrict__ l4,
    const float* __restrict__ W1, const float* __restrict__ b1,
    const float* __restrict__ W2, const float* __restrict__ b2,
    const float* __restrict__ W3, const float* __restrict__ b3,
    const float* __restrict__ W4, const float* __restrict__ b4,
    float* __restrict__ out)
{
    extern __shared__ float4 sx[];        // up to 4096 float4 = 65536 B (half tile)
    __shared__ float red[16][2];
    __shared__ float s_conf[4];
    __shared__ float s_uf[2];

    const int b     = blockIdx.x >> 1;
    const int h     = blockIdx.x & 1;     // 0: G1+G2 (ch 0..29), 1: G3+G4 (ch 30..61)
    const int tid   = threadIdx.x;
    const int lane  = tid & 31;
    const int warp  = tid >> 5;
    const int cbase = h ? 30 : 0;
    const int split = h ? 20 : 12;        // local channel where 2nd group starts
    const int n4    = (h ? 32 : 30) * 128;

    // ---- hoisted scalar loads (latency hides under phase 1) ----
    float la0 = -1e30f, la1 = -1e30f;
    if (warp >= 1 && warp <= 4) {
        const float* lg = (warp == 1 ? l1 : warp == 2 ? l2 : warp == 3 ? l3 : l4)
                          + (size_t)b * NCLS;
        if (lane < NCLS)      la0 = __ldg(lg + lane);
        if (lane + 32 < NCLS) la1 = __ldg(lg + lane + 32);
    }
    float my_bias = 0.f;
    if (warp == 0 && lane < 2) {
        const float* bp = h ? (lane ? b4 : b3) : (lane ? b2 : b1);
        my_bias = __ldg(bp);
    }

    const float4* xav = (const float4*)(h ? x3 : x1);   // first group of this half
    const float4* xbv = (const float4*)(h ? x4 : x2);   // second group
    const float4* wav = (const float4*)(h ? W3 : W1);
    const float4* wbv = (const float4*)(h ? W4 : W2);
    const int cha = h ? 20 : 12;          // channels in first group
    const int chb = h ? 12 : 18;          // channels in second group
    const float4* gvp = (const float4*)g + (size_t)b * TOT4;
    float4* ovp = (float4*)(out + 4 * NBATCH) + (size_t)b * TOT4;

    const uint32_t sbase = (uint32_t)__cvta_generic_to_shared(sx);

    // ---- Phase 1a: fire-and-forget x -> smem (cp.async) + g -> regs; max MLP ----
    float4 gv[8];
#pragma unroll
    for (int k = 0; k < 8; k++) {
        const int idx = tid + THREADS * k;
        if (idx < n4) {
            const int c = idx >> 7;       // local channel
            const int d = idx & 127;
            const float4* xp;
            if (c < split) xp = xav + ((size_t)b * cha + c        ) * 128 + d;
            else           xp = xbv + ((size_t)b * chb + (c-split)) * 128 + d;
            cp_async16(sbase + idx * 16, xp);
            const int r = c_orow[cbase + c];
            gv[k] = __ldcs(gvp + r * 128 + d);
        }
    }
    asm volatile("cp.async.commit_group;" ::: "memory");
    asm volatile("cp.async.wait_group 0;" ::: "memory");

    // ---- Phase 1b: dot from smem (own writes, visible post-wait) ----
    float pa = 0.f, pb = 0.f;
#pragma unroll
    for (int k = 0; k < 8; k++) {
        const int idx = tid + THREADS * k;
        if (idx < n4) {
            const int c = idx >> 7;
            const int d = idx & 127;
            const float4* wp;
            if (c < split) wp = wav + c * 128 + d;
            else           wp = wbv + (c - split) * 128 + d;
            float4 v = sx[idx];
            float4 w = *wp;
            float dp = v.x * w.x + v.y * w.y + v.z * w.z + v.w * w.w;
            pa += (c < split) ? dp : 0.f;
            pb += (c < split) ? 0.f : dp;
        }
    }

    // ---- confidences (warps 1..4; logits resident; fast-math) ----
    if (warp >= 1 && warp <= 4) {
        const int q = warp - 1;
        float m = fmaxf(la0, la1);
#pragma unroll
        for (int o = 16; o > 0; o >>= 1)
            m = fmaxf(m, __shfl_xor_sync(0xffffffffu, m, o));
        float e0 = (lane < NCLS)      ? __expf(la0 - m) : 0.f;
        float e1 = (lane + 32 < NCLS) ? __expf(la1 - m) : 0.f;
        float s = e0 + e1;
#pragma unroll
        for (int o = 16; o > 0; o >>= 1)
            s += __shfl_xor_sync(0xffffffffu, s, o);
        const float inv = 1.f / s;           // == max_p
        float pp0 = e0 * inv, pp1 = e1 * inv;
        float t = 0.f;
        if (lane < NCLS)      t += pp0 * __logf(pp0 + 1e-8f);
        if (lane + 32 < NCLS) t += pp1 * __logf(pp1 + 1e-8f);
#pragma unroll
        for (int o = 16; o > 0; o >>= 1)
            t += __shfl_xor_sync(0xffffffffu, t, o);
        const float norm_ent = (-t) * INV_LOG_NCLS;
        if (lane == 0) s_conf[q] = inv * (1.f - norm_ent);
    }

    // ---- dot partial reduce (all 16 warps) ----
#pragma unroll
    for (int o = 16; o > 0; o >>= 1) {
        pa += __shfl_xor_sync(0xffffffffu, pa, o);
        pb += __shfl_xor_sync(0xffffffffu, pb, o);
    }
    if (lane == 0) { red[warp][0] = pa; red[warp][1] = pb; }
    __syncthreads();   // covers red[] and s_conf[]

    // ---- finalize: warp 0 ----
    if (warp == 0) {
        const bool ok = lane < 16;
        float va = ok ? red[lane][0] : 0.f;
        float vb = ok ? red[lane][1] : 0.f;
#pragma unroll
        for (int o = 8; o > 0; o >>= 1) {
            va += __shfl_xor_sync(0xffffffffu, va, o);
            vb += __shfl_xor_sync(0xffffffffu, vb, o);
        }
        if (lane < 2) {
            const float c0 = s_conf[0], c1 = s_conf[1], c2 = s_conf[2], c3 = s_conf[3];
            const float cm = fmaxf(fmaxf(c0, c1), fmaxf(c2, c3));
            const float e0 = __expf(c0 - cm), e1 = __expf(c1 - cm),
                        e2 = __expf(c2 - cm), e3 = __expf(c3 - cm);
            const float inv = 1.f / (e0 + e1 + e2 + e3);
            const int gi = 2 * h + lane;                  // global group index
            const float my_e = (gi == 0 ? e0 : gi == 1 ? e1 : gi == 2 ? e2 : e3);
            const float my_v = __shfl_sync(0x3u, lane == 0 ? va : vb, lane);
            const float nc = my_e * inv;
            out[(size_t)gi * NBATCH + b] = nc;            // norm_conf column
            const float u = 1.f / (1.f + __expf(-(my_v + my_bias)));
            s_uf[lane] = u * nc;
        }
    }
    __syncthreads();

    // ---- Phase 4: trans-half = (x + g) * u_final ----
    const float ua = s_uf[0], ub = s_uf[1];
#pragma unroll
    for (int k = 0; k < 8; k++) {
        const int idx = tid + THREADS * k;
        if (idx < n4) {
            const int c = idx >> 7;
            const int d = idx & 127;
            const int r = c_orow[cbase + c];
            const float sc = (c < split) ? ua : ub;
            float4 v  = sx[idx];
            float4 gk = gv[k];
            float4 o;
            o.x = (v.x + gk.x) * sc;
            o.y = (v.y + gk.y) * sc;
            o.z = (v.z + gk.z) * sc;
            o.w = (v.w + gk.w) * sc;
            __stcs(ovp + r * 128 + d, o);
        }
    }
}

extern "C" void kernel_launch(void* const* d_in, const int* in_sizes, int n_in,
                              void* d_out, int out_size)
{
    const float* x1 = (const float*)d_in[0];
    const float* x2 = (const float*)d_in[1];
    const float* x3 = (const float*)d_in[2];
    const float* x4 = (const float*)d_in[3];
    const float* g  = (const float*)d_in[4];
    const float* l1 = (const float*)d_in[5];
    const float* l2 = (const float*)d_in[6];
    const float* l3 = (const float*)d_in[7];
    const float* l4 = (const float*)d_in[8];
    const float* W1 = (const float*)d_in[9];
    const float* b1 = (const float*)d_in[10];
    const float* W2 = (const float*)d_in[11];
    const float* b2 = (const float*)d_in[12];
    const float* W3 = (const float*)d_in[13];
    const float* b3 = (const float*)d_in[14];
    const float* W4 = (const float*)d_in[15];
    const float* b4 = (const float*)d_in[16];
    float* out = (float*)d_out;

    const int smem = 32 * 512 * (int)sizeof(float);   // 65536 B (worst half)
    cudaFuncSetAttribute(lgl_fused_kernel,
                         cudaFuncAttributeMaxDynamicSharedMemorySize, smem);

    lgl_fused_kernel<<<NBATCH * 2, THREADS, smem>>>(
        x1, x2, x3, x4, g, l1, l2, l3, l4,
        W1, b1, W2, b2, W3, b3, W4, b4, out);
}

// round 14
// speedup vs baseline: 1.2472x; 1.0040x over previous
#include <cuda_runtime.h>
#include <cstdint>

#define NBATCH 2048
#define NCLS 62
#define THREADS 512
#define TOT4 (62 * 128)       // float4 per batch across all 62 channels
#define INV_LOG_NCLS 0.24233102611194615f   // 1 / ln(62)

// concat channel c (global 0..61) -> output row r (verified)
__constant__ int c_orow[62] = {
    1, 0, 2, 3, 4, 6, 7, 8, 9, 10, 11, 12,
    5, 13, 14, 15, 21, 22, 23, 24, 30, 31, 32, 33, 39, 40, 41, 42, 48, 49,
    16, 17, 18, 19, 20, 25, 26, 27, 28, 29, 34, 35, 36, 37, 38, 43, 44, 45, 46, 47,
    50, 51, 52, 53, 54, 55, 56, 57, 58, 59, 60, 61
};

__device__ __forceinline__ void cp_async16(uint32_t dst_smem, const void* src) {
    asm volatile("cp.async.cg.shared.global [%0], [%1], 16;"
                 :: "r"(dst_smem), "l"(src) : "memory");
}

__global__ __launch_bounds__(THREADS, 2)
void lgl_fused_kernel(
    const float* __restrict__ x1, const float* __restrict__ x2,
    const float* __restrict__ x3, const float* __restrict__ x4,
    const float* __restrict__ g,
    const float* __restrict__ l1, const float* __restrict__ l2,
    const float* __restrict__ l3, const float* __restrict__ l4,
    const float* __restrict__ W1, const float* __restrict__ b1,
    const float* __restrict__ W2, const float* __restrict__ b2,
    const float* __restrict__ W3, const float* __restrict__ b3,
    const float* __restrict__ W4, const float* __restrict__ b4,
    float* __restrict__ out)
{
    extern __shared__ float4 sx[];        // up to 4096 float4 = 65536 B (half tile)
    __shared__ float red[16][2];
    __shared__ float s_conf[4];
    __shared__ float s_uf[2];

    const int b     = blockIdx.x >> 1;
    const int h     = blockIdx.x & 1;     // 0: G1+G2 (ch 0..29), 1: G3+G4 (ch 30..61)
    const int tid   = threadIdx.x;
    const int lane  = tid & 31;
    const int warp  = tid >> 5;
    const int cbase = h ? 30 : 0;
    const int split = h ? 20 : 12;        // local channel where 2nd group starts
    const int n4    = (h ? 32 : 30) * 128;

    // ---- hoisted scalar loads (latency hides under phase 1) ----
    float la0 = -1e30f, la1 = -1e30f;
    if (warp >= 1 && warp <= 4) {
        const float* lg = (warp == 1 ? l1 : warp == 2 ? l2 : warp == 3 ? l3 : l4)
                          + (size_t)b * NCLS;
        if (lane < NCLS)      la0 = __ldg(lg + lane);
        if (lane + 32 < NCLS) la1 = __ldg(lg + lane + 32);
    }
    float my_bias = 0.f;
    if (warp == 0 && lane < 2) {
        const float* bp = h ? (lane ? b4 : b3) : (lane ? b2 : b1);
        my_bias = __ldg(bp);
    }

    const float4* xav = (const float4*)(h ? x3 : x1);   // first group of this half
    const float4* xbv = (const float4*)(h ? x4 : x2);   // second group
    const float4* wav = (const float4*)(h ? W3 : W1);
    const float4* wbv = (const float4*)(h ? W4 : W2);
    const int cha = h ? 20 : 12;          // channels in first group
    const int chb = h ? 12 : 18;          // channels in second group
    const float4* gvp = (const float4*)g + (size_t)b * TOT4;
    float4* ovp = (float4*)(out + 4 * NBATCH) + (size_t)b * TOT4;

    const uint32_t sbase = (uint32_t)__cvta_generic_to_shared(sx);

    // ---- Phase 1a: fire-and-forget x -> smem (cp.async, 2 groups) + g -> regs ----
    float4 gv[8];
#pragma unroll
    for (int k = 0; k < 4; k++) {
        const int idx = tid + THREADS * k;
        if (idx < n4) {
            const int c = idx >> 7;       // local channel
            const int d = idx & 127;
            const float4* xp;
            if (c < split) xp = xav + ((size_t)b * cha + c        ) * 128 + d;
            else           xp = xbv + ((size_t)b * chb + (c-split)) * 128 + d;
            cp_async16(sbase + idx * 16, xp);
            const int r = c_orow[cbase + c];
            gv[k] = __ldcs(gvp + r * 128 + d);
        }
    }
    asm volatile("cp.async.commit_group;" ::: "memory");
#pragma unroll
    for (int k = 4; k < 8; k++) {
        const int idx = tid + THREADS * k;
        if (idx < n4) {
            const int c = idx >> 7;
            const int d = idx & 127;
            const float4* xp;
            if (c < split) xp = xav + ((size_t)b * cha + c        ) * 128 + d;
            else           xp = xbv + ((size_t)b * chb + (c-split)) * 128 + d;
            cp_async16(sbase + idx * 16, xp);
            const int r = c_orow[cbase + c];
            gv[k] = __ldcs(gvp + r * 128 + d);
        }
    }
    asm volatile("cp.async.commit_group;" ::: "memory");

    // ---- Phase 1b: dot from smem, pipelined against the copy tail ----
    float pa = 0.f, pb = 0.f;
    asm volatile("cp.async.wait_group 1;" ::: "memory");   // group A landed
#pragma unroll
    for (int k = 0; k < 4; k++) {
        const int idx = tid + THREADS * k;
        if (idx < n4) {
            const int c = idx >> 7;
            const int d = idx & 127;
            const float4* wp;
            if (c < split) wp = wav + c * 128 + d;
            else           wp = wbv + (c - split) * 128 + d;
            float4 v = sx[idx];
            float4 w = *wp;
            float dp = v.x * w.x + v.y * w.y + v.z * w.z + v.w * w.w;
            pa += (c < split) ? dp : 0.f;
            pb += (c < split) ? 0.f : dp;
        }
    }
    asm volatile("cp.async.wait_group 0;" ::: "memory");   // group B landed
#pragma unroll
    for (int k = 4; k < 8; k++) {
        const int idx = tid + THREADS * k;
        if (idx < n4) {
            const int c = idx >> 7;
            const int d = idx & 127;
            const float4* wp;
            if (c < split) wp = wav + c * 128 + d;
            else           wp = wbv + (c - split) * 128 + d;
            float4 v = sx[idx];
            float4 w = *wp;
            float dp = v.x * w.x + v.y * w.y + v.z * w.z + v.w * w.w;
            pa += (c < split) ? dp : 0.f;
            pb += (c < split) ? 0.f : dp;
        }
    }

    // ---- confidences (warps 1..4; logits resident; fast-math) ----
    if (warp >= 1 && warp <= 4) {
        const int q = warp - 1;
        float m = fmaxf(la0, la1);
#pragma unroll
        for (int o = 16; o > 0; o >>= 1)
            m = fmaxf(m, __shfl_xor_sync(0xffffffffu, m, o));
        float e0 = (lane < NCLS)      ? __expf(la0 - m) : 0.f;
        float e1 = (lane + 32 < NCLS) ? __expf(la1 - m) : 0.f;
        float s = e0 + e1;
#pragma unroll
        for (int o = 16; o > 0; o >>= 1)
            s += __shfl_xor_sync(0xffffffffu, s, o);
        const float inv = 1.f / s;           // == max_p
        float pp0 = e0 * inv, pp1 = e1 * inv;
        float t = 0.f;
        if (lane < NCLS)      t += pp0 * __logf(pp0 + 1e-8f);
        if (lane + 32 < NCLS) t += pp1 * __logf(pp1 + 1e-8f);
#pragma unroll
        for (int o = 16; o > 0; o >>= 1)
            t += __shfl_xor_sync(0xffffffffu, t, o);
        const float norm_ent = (-t) * INV_LOG_NCLS;
        if (lane == 0) s_conf[q] = inv * (1.f - norm_ent);
    }

    // ---- dot partial reduce (all 16 warps) ----
#pragma unroll
    for (int o = 16; o > 0; o >>= 1) {
        pa += __shfl_xor_sync(0xffffffffu, pa, o);
        pb += __shfl_xor_sync(0xffffffffu, pb, o);
    }
    if (lane == 0) { red[warp][0] = pa; red[warp][1] = pb; }
    __syncthreads();   // covers red[] and s_conf[]

    // ---- finalize: warp 0 ----
    if (warp == 0) {
        const bool ok = lane < 16;
        float va = ok ? red[lane][0] : 0.f;
        float vb = ok ? red[lane][1] : 0.f;
#pragma unroll
        for (int o = 8; o > 0; o >>= 1) {
            va += __shfl_xor_sync(0xffffffffu, va, o);
            vb += __shfl_xor_sync(0xffffffffu, vb, o);
        }
        if (lane < 2) {
            const float c0 = s_conf[0], c1 = s_conf[1], c2 = s_conf[2], c3 = s_conf[3];
            const float cm = fmaxf(fmaxf(c0, c1), fmaxf(c2, c3));
            const float e0 = __expf(c0 - cm), e1 = __expf(c1 - cm),
                        e2 = __expf(c2 - cm), e3 = __expf(c3 - cm);
            const float inv = 1.f / (e0 + e1 + e2 + e3);
            const int gi = 2 * h + lane;                  // global group index
            const float my_e = (gi == 0 ? e0 : gi == 1 ? e1 : gi == 2 ? e2 : e3);
            const float my_v = __shfl_sync(0x3u, lane == 0 ? va : vb, lane);
            const float nc = my_e * inv;
            out[(size_t)gi * NBATCH + b] = nc;            // norm_conf column
            const float u = 1.f / (1.f + __expf(-(my_v + my_bias)));
            s_uf[lane] = u * nc;
        }
    }
    __syncthreads();

    // ---- Phase 4: trans-half = (x + g) * u_final ----
    const float ua = s_uf[0], ub = s_uf[1];
#pragma unroll
    for (int k = 0; k < 8; k++) {
        const int idx = tid + THREADS * k;
        if (idx < n4) {
            const int c = idx >> 7;
            const int d = idx & 127;
            const int r = c_orow[cbase + c];
            const float sc = (c < split) ? ua : ub;
            float4 v  = sx[idx];
            float4 gk = gv[k];
            float4 o;
            o.x = (v.x + gk.x) * sc;
            o.y = (v.y + gk.y) * sc;
            o.z = (v.z + gk.z) * sc;
            o.w = (v.w + gk.w) * sc;
            __stcs(ovp + r * 128 + d, o);
        }
    }
}

extern "C" void kernel_launch(void* const* d_in, const int* in_sizes, int n_in,
                              void* d_out, int out_size)
{
    const float* x1 = (const float*)d_in[0];
    const float* x2 = (const float*)d_in[1];
    const float* x3 = (const float*)d_in[2];
    const float* x4 = (const float*)d_in[3];
    const float* g  = (const float*)d_in[4];
    const float* l1 = (const float*)d_in[5];
    const float* l2 = (const float*)d_in[6];
    const float* l3 = (const float*)d_in[7];
    const float* l4 = (const float*)d_in[8];
    const float* W1 = (const float*)d_in[9];
    const float* b1 = (const float*)d_in[10];
    const float* W2 = (const float*)d_in[11];
    const float* b2 = (const float*)d_in[12];
    const float* W3 = (const float*)d_in[13];
    const float* b3 = (const float*)d_in[14];
    const float* W4 = (const float*)d_in[15];
    const float* b4 = (const float*)d_in[16];
    float* out = (float*)d_out;

    const int smem = 32 * 512 * (int)sizeof(float);   // 65536 B (worst half)
    cudaFuncSetAttribute(lgl_fused_kernel,
                         cudaFuncAttributeMaxDynamicSharedMemorySize, smem);

    lgl_fused_kernel<<<NBATCH * 2, THREADS, smem>>>(
        x1, x2, x3, x4, g, l1, l2, l3, l4,
        W1, b1, W2, b2, W3, b3, W4, b4, out);
}